// round 13
// baseline (speedup 1.0000x reference)
#include <cuda_runtime.h>
#include <cuda_bf16.h>
#include <cstdint>

// ---------------------------------------------------------------------------
// AdaptiveEMAModel. Committed: vocab-table preprocess (R12 occ-2 tiling),
// single-bar branchless scan. R13 change: scan runs 512 threads (4/row,
// 32 cols each) for 4 warps/SMSP latency hiding; quarter-pitch-36 kn ring
// (conflict-free, 16B-aligned LDS.128).
// ---------------------------------------------------------------------------

typedef unsigned long long u64t;

__device__ __forceinline__ u64t pk2(float lo, float hi) {
    u64t r;
    asm("mov.b64 %0, {%1, %2};" : "=l"(r) : "f"(lo), "f"(hi));
    return r;
}
__device__ __forceinline__ void fma2(u64t& d, u64t a, u64t b) {
    asm("fma.rn.f32x2 %0, %1, %2, %0;" : "+l"(d) : "l"(a), "l"(b));
}
__device__ __forceinline__ float2 upk(u64t v) {
    float2 f;
    asm("mov.b64 {%0, %1}, %2;" : "=f"(f.x), "=f"(f.y) : "l"(v));
    return f;
}
__device__ __forceinline__ float hsum(u64t v) {
    float2 f = upk(v);
    return f.x + f.y;
}

#define Bn   64
#define Ln   2048
#define Hn   128
#define H2n  256
#define Vn   32000
#define NTOK (Bn * Ln)

// ------------------------- global scratch ----------------------------------
__device__ __align__(16) float g_y[(size_t)Vn * H2n];      // 32.8 MB
__device__ __align__(16) float g_part[(size_t)Vn * Hn];    // 16.4 MB
__device__ __align__(16) float g_hln[(size_t)Vn * Hn];     // 16.4 MB
__device__ __align__(16) float g_Kv[(size_t)Vn * Hn];      // raw k per vocab
__device__ __align__(16) float g_KNv[(size_t)Vn * Hn];     // normalized k
__device__ __align__(16) float g_THv[Vn];                  // (0.4*||k||)^2
__device__ __align__(16) float g_read[Bn * Hn];
__device__ __align__(16) float g_r2[Bn * Hn];
__device__ int g_is64;

// ------------------------- K0: detect seq dtype ----------------------------
__global__ void k0_detect(const unsigned int* __restrict__ sw) {
    int t = threadIdx.x;
    int nz = (sw[2 * t + 1] != 0u) ? 1 : 0;
    nz = __syncthreads_or(nz);
    if (t == 0) g_is64 = nz ? 0 : 1;
}

// ------------------------- shared GEMM core (32tok x 128out x 128red) ------
#define KVT_SMEM ((128 * 132 + 32 * 132) * 4)

__device__ __forceinline__ void gemm_core(const float* __restrict__ Wsm,
                                          const float* __restrict__ Xsm,
                                          int tg, int lane, u64t acc[4][4]) {
    const float4* W4 = (const float4*)Wsm;
    const float4* X4 = (const float4*)Xsm;
#pragma unroll
    for (int i = 0; i < 4; ++i)
#pragma unroll
        for (int j = 0; j < 4; ++j) acc[i][j] = 0ull;
#pragma unroll 4
    for (int hh = 0; hh < 32; ++hh) {
        u64t wl[4], wh[4];
#pragma unroll
        for (int j = 0; j < 4; ++j) {
            float4 wq = W4[(lane + 32 * j) * 33 + hh];
            wl[j] = pk2(wq.x, wq.y);
            wh[j] = pk2(wq.z, wq.w);
        }
#pragma unroll
        for (int i = 0; i < 4; ++i) {
            float4 xq = X4[(tg + i) * 33 + hh];
            u64t xl = pk2(xq.x, xq.y), xh = pk2(xq.z, xq.w);
#pragma unroll
            for (int j = 0; j < 4; ++j) {
                fma2(acc[i][j], xl, wl[j]);
                fma2(acc[i][j], xh, wh[j]);
            }
        }
    }
}

__device__ __forceinline__ void stage_w(float* Wsm, const float* __restrict__ src,
                                        int rstride, int tid) {
    for (int i = tid; i < 128 * 32; i += 256) {
        int r = i >> 5, c = i & 31;
        *(float4*)(Wsm + r * 132 + 4 * c) = *(const float4*)(src + (size_t)r * rstride + 4 * c);
    }
}
__device__ __forceinline__ void stage_x(float* Xsm, const float* __restrict__ src,
                                        int rstride, int tid) {
    for (int i = tid; i < 32 * 32; i += 256) {
        int tk = i >> 5, q = i & 31;
        *(float4*)(Xsm + tk * 132 + 4 * q) = *(const float4*)(src + (size_t)tk * rstride + 4 * q);
    }
}

// ------------------------- KV1: FFN layer 1 (one output half) --------------
__global__ __launch_bounds__(256, 2)
void kv1(const float* __restrict__ ew, const float* __restrict__ w1,
         const float* __restrict__ b1, int obase) {
    extern __shared__ float sm[];
    float* W = sm;
    float* X = sm + 128 * 132;

    const int tid = threadIdx.x;
    const int lane = tid & 31;
    const int tg = (tid >> 5) * 4;

    stage_w(W, w1 + (size_t)obase * 128, 128, tid);
    float bb[4];
#pragma unroll
    for (int j = 0; j < 4; ++j) bb[j] = b1[obase + lane + 32 * j];
    __syncthreads();

    for (int tile = blockIdx.x; tile < Vn / 32; tile += gridDim.x) {
        const int v0 = tile * 32;
        stage_x(X, ew + (size_t)v0 * 128, 128, tid);
        __syncthreads();

        u64t acc[4][4];
        gemm_core(W, X, tg, lane, acc);

#pragma unroll
        for (int i = 0; i < 4; ++i)
#pragma unroll
            for (int j = 0; j < 4; ++j) {
                float y = hsum(acc[i][j]) + bb[j];
                g_y[(size_t)(v0 + tg + i) * H2n + obase + lane + 32 * j] = fmaxf(y, 0.0f);
            }
        __syncthreads();
    }
}

// ------------------------- KV2a: FFN layer 2, reduction half 0 -> partial --
__global__ __launch_bounds__(256, 2)
void kv2a(const float* __restrict__ w2) {
    extern __shared__ float sm[];
    float* W = sm;
    float* X = sm + 128 * 132;

    const int tid = threadIdx.x;
    const int lane = tid & 31;
    const int tg = (tid >> 5) * 4;

    stage_w(W, w2, 256, tid);
    __syncthreads();

    for (int tile = blockIdx.x; tile < Vn / 32; tile += gridDim.x) {
        const int v0 = tile * 32;
        stage_x(X, g_y + (size_t)v0 * H2n, H2n, tid);
        __syncthreads();

        u64t acc[4][4];
        gemm_core(W, X, tg, lane, acc);

#pragma unroll
        for (int i = 0; i < 4; ++i)
#pragma unroll
            for (int j = 0; j < 4; ++j)
                g_part[(size_t)(v0 + tg + i) * Hn + lane + 32 * j] = hsum(acc[i][j]);
        __syncthreads();
    }
}

// ------------------------- KV2b: reduction half 1 + bias + residual + LN ---
__global__ __launch_bounds__(256, 2)
void kv2b(const float* __restrict__ ew, const float* __restrict__ w2,
          const float* __restrict__ b2,
          const float* __restrict__ lng, const float* __restrict__ lnb) {
    extern __shared__ float sm[];
    float* W = sm;
    float* X = sm + 128 * 132;

    const int tid = threadIdx.x;
    const int lane = tid & 31;
    const int tg = (tid >> 5) * 4;

    stage_w(W, w2 + 128, 256, tid);
    float b2r[4], gr[4], br[4];
#pragma unroll
    for (int j = 0; j < 4; ++j) {
        b2r[j] = b2[lane + 32 * j];
        gr[j] = lng[lane + 32 * j];
        br[j] = lnb[lane + 32 * j];
    }
    __syncthreads();

    for (int tile = blockIdx.x; tile < Vn / 32; tile += gridDim.x) {
        const int v0 = tile * 32;
        stage_x(X, g_y + (size_t)v0 * H2n + 128, H2n, tid);
        __syncthreads();

        u64t acc[4][4];
        gemm_core(W, X, tg, lane, acc);

#pragma unroll
        for (int i = 0; i < 4; ++i) {
            const size_t tok = (size_t)(v0 + tg + i);
            float x[4];
#pragma unroll
            for (int j = 0; j < 4; ++j)
                x[j] = hsum(acc[i][j]) + g_part[tok * Hn + lane + 32 * j]
                     + b2r[j] + ew[tok * 128 + lane + 32 * j];
            float s = x[0] + x[1] + x[2] + x[3];
#pragma unroll
            for (int off = 16; off; off >>= 1) s += __shfl_xor_sync(0xffffffffu, s, off);
            float mu = s * (1.0f / 128.0f);
            float vs = 0.0f;
#pragma unroll
            for (int j = 0; j < 4; ++j) { float dv = x[j] - mu; vs += dv * dv; }
#pragma unroll
            for (int off = 16; off; off >>= 1) vs += __shfl_xor_sync(0xffffffffu, vs, off);
            float den = sqrtf(vs * (1.0f / 128.0f) + 1e-5f);
#pragma unroll
            for (int j = 0; j < 4; ++j)
                g_hln[tok * Hn + lane + 32 * j] = (x[j] - mu) / den * gr[j] + br[j];
        }
        __syncthreads();
    }
}

// ------------------------- KV3: kproj + norm/kn/threshold ------------------
__global__ __launch_bounds__(256, 2)
void kv3(const float* __restrict__ kpw) {
    extern __shared__ float sm[];
    float* W = sm;
    float* X = sm + 128 * 132;

    const int tid = threadIdx.x;
    const int lane = tid & 31;
    const int tg = (tid >> 5) * 4;

    stage_w(W, kpw, 128, tid);
    __syncthreads();

    for (int tile = blockIdx.x; tile < Vn / 32; tile += gridDim.x) {
        const int v0 = tile * 32;
        stage_x(X, g_hln + (size_t)v0 * Hn, Hn, tid);
        __syncthreads();

        u64t acc[4][4];
        gemm_core(W, X, tg, lane, acc);

#pragma unroll
        for (int i = 0; i < 4; ++i) {
            const size_t tok = (size_t)(v0 + tg + i);
            float kv[4];
            float s = 0.0f;
#pragma unroll
            for (int j = 0; j < 4; ++j) {
                kv[j] = hsum(acc[i][j]);
                g_Kv[tok * Hn + lane + 32 * j] = kv[j];
                s += kv[j] * kv[j];
            }
#pragma unroll
            for (int off = 16; off; off >>= 1) s += __shfl_xor_sync(0xffffffffu, s, off);
            float nm = fmaxf(sqrtf(s), 1e-12f);
#pragma unroll
            for (int j = 0; j < 4; ++j)
                g_KNv[tok * Hn + lane + 32 * j] = kv[j] / nm;
            if (lane == 0) {
                float t1 = 0.4f * nm;
                g_THv[tok] = t1 * t1;
            }
        }
        __syncthreads();
    }
}

// ------------------------- K2: delta-rule scan, 512 threads ----------------
// 64 CTAs x 512 threads (16 warps = 4/SMSP). Thread quartet (4q+0..3) owns
// M row r = tid>>2; thread covers cols q*32..q*32+31 as 16 f32x2 regs.
// kn ring slot layout: column j at kns[slot][36*(j>>5) + (j&31)] — quarter
// pitch 36 floats = 144B (16B aligned, banks {0,4,8,12}+4i: conflict-free).
// Single bar/step; branchless gate; raw k/kn/threshold via L2-hot tables.
__global__ __launch_bounds__(512, 1)
void k2_scan(const void* __restrict__ seq) {
    const int b = blockIdx.x;
    const int tid = threadIdx.x;
    const int lane = tid & 31;
    const int w = tid >> 5;        // 16 warps
    const int row = tid >> 2;      // 128 rows
    const int q = tid & 3;         // column quarter
    const int qoff = q * 36;

    __shared__ int   idxs[Ln];
    __shared__ float ths[Ln];
    __shared__ __align__(16) float kns[8][144];   // kn ring, slot = t & 7
    __shared__ __align__(16) float red[2][16];

    const int is64 = g_is64;
    for (int i = tid; i < Ln; i += 512) {
        long long idx = is64 ? ((const long long*)seq)[(size_t)b * Ln + i]
                             : (long long)((const int*)seq)[(size_t)b * Ln + i];
        idxs[i] = (int)idx;
        ths[i] = g_THv[idx];
    }
    __syncthreads();

    const int posw = 36 * (row >> 5) + (row & 31);   // write slot for kn[row]
    if (q == 0) {
        kns[0][posw] = g_KNv[(size_t)idxs[0] * Hn + row];
        kns[1][posw] = g_KNv[(size_t)idxs[1] * Hn + row];
    }
    float Lprev = g_KNv[(size_t)idxs[2] * Hn + row];   // kn[2] in flight
    float kcur = g_Kv[(size_t)idxs[0] * Hn + row];     // raw k_t (own row)
    float knx1 = g_Kv[(size_t)idxs[1] * Hn + row];
    float knx2 = g_Kv[(size_t)idxs[2] * Hn + row];
    float thc  = ths[0];

    u64t M[16];
#pragma unroll
    for (int c = 0; c < 16; ++c) M[c] = 0ull;
    __syncthreads();

#pragma unroll 2
    for (int t = 0; t < Ln - 1; ++t) {
        // ---- global prefetches (3 steps ahead, L2-hot tables) ----
        const int tp = t + 3;
        float Lnew = 0.0f;
        if (tp < Ln - 1)       Lnew = g_KNv[(size_t)idxs[tp] * Hn + row];
        else if (tp == Ln - 1) Lnew = g_Kv[(size_t)idxs[Ln - 1] * Hn + row];  // raw q
        const int tk = (tp < Ln) ? tp : Ln - 1;
        float knew = g_Kv[(size_t)idxs[tk] * Hn + row];
        float thn = ths[(t + 1 < Ln) ? t + 1 : t];

        // ring store: kn[t+2] (loaded 2 iters ago); skew<=1 -> safe
        if (q == 0) kns[(t + 2) & 7][posw] = Lprev;

        // ---- matvec: vp(quarter) = M . kn_t (4 accs, 4-deep chains) ----
        const float4* knT4 = (const float4*)(kns[t & 7] + qoff);
        u64t kr[16];
        u64t a0 = 0ull, a1 = 0ull, a2 = 0ull, a3 = 0ull;
#pragma unroll
        for (int cc = 0; cc < 4; ++cc) {
            float4 v0 = knT4[2 * cc];
            float4 v1 = knT4[2 * cc + 1];
            kr[4 * cc]     = pk2(v0.x, v0.y);
            kr[4 * cc + 1] = pk2(v0.z, v0.w);
            kr[4 * cc + 2] = pk2(v1.x, v1.y);
            kr[4 * cc + 3] = pk2(v1.z, v1.w);
            fma2(a0, M[4 * cc],     kr[4 * cc]);
            fma2(a1, M[4 * cc + 1], kr[4 * cc + 1]);
            fma2(a2, M[4 * cc + 2], kr[4 * cc + 2]);
            fma2(a3, M[4 * cc + 3], kr[4 * cc + 3]);
        }
        float vph = (hsum(a0) + hsum(a1)) + (hsum(a2) + hsum(a3));
        vph += __shfl_xor_sync(0xffffffffu, vph, 1);
        vph += __shfl_xor_sync(0xffffffffu, vph, 2);
        float d = kcur - vph;

        // ---- ||d||^2: d replicated in quartet -> 3-shuffle tree over rows --
        float dsq = d * d;
        dsq += __shfl_xor_sync(0xffffffffu, dsq, 4);
        dsq += __shfl_xor_sync(0xffffffffu, dsq, 8);
        dsq += __shfl_xor_sync(0xffffffffu, dsq, 16);
        if (lane == 0) red[t & 1][w] = dsq;
        __syncthreads();   // the single barrier per step

        float4 r0 = *(const float4*)&red[t & 1][0];
        float4 r1 = *(const float4*)&red[t & 1][4];
        float4 r2 = *(const float4*)&red[t & 1][8];
        float4 r3 = *(const float4*)&red[t & 1][12];
        float dd = (((r0.x + r0.y) + (r0.z + r0.w)) + ((r1.x + r1.y) + (r1.z + r1.w)))
                 + (((r2.x + r2.y) + (r2.z + r2.w)) + ((r3.x + r3.y) + (r3.z + r3.w)));

        // ---- branchless gate + rank-1 update (fma w/ 0 is bit-neutral) ----
        float s = (dd >= thc) ? d * (1.0f / 2048.0f) : 0.0f;
        u64t s2 = pk2(s, s);
#pragma unroll
        for (int c = 0; c < 16; ++c) fma2(M[c], s2, kr[c]);

        kcur = knx1; knx1 = knx2; knx2 = knew;
        thc = thn;
        Lprev = Lnew;
    }

    // ---- read = M @ q (raw k_2047, staged in ring slot (Ln-1)&7) ----
    __syncthreads();
    {
        const float4* q4 = (const float4*)(kns[(Ln - 1) & 7] + qoff);
        u64t a0 = 0ull, a1 = 0ull;
#pragma unroll
        for (int cc = 0; cc < 8; ++cc) {
            float4 v = q4[cc];
            fma2(a0, M[2 * cc], pk2(v.x, v.y));
            fma2(a1, M[2 * cc + 1], pk2(v.z, v.w));
        }
        float vph = hsum(a0) + hsum(a1);
        vph += __shfl_xor_sync(0xffffffffu, vph, 1);
        vph += __shfl_xor_sync(0xffffffffu, vph, 2);
        if (q == 0) g_read[b * Hn + row] = vph;
    }
}

// ------------------------- K2b: r2 = read @ rp_w^T + rp_b ------------------
__global__ void k2b(const float* __restrict__ rpw, const float* __restrict__ rpb) {
    __shared__ __align__(16) float rs[128];
    const int b = blockIdx.x, tid = threadIdx.x;
    rs[tid] = g_read[b * Hn + tid];
    __syncthreads();
    const u64t* rp = (const u64t*)rs;
    u64t acc = 0ull;
#pragma unroll 8
    for (int j2 = 0; j2 < 64; ++j2) {
        u64t wv = *(const u64t*)(rpw + tid * 128 + 2 * j2);
        fma2(acc, rp[j2], wv);
    }
    g_r2[b * Hn + tid] = hsum(acc) + rpb[tid];
}

// ------------------------- K3: out = r2 @ out_w^T + out_b ------------------
#define K3_SMEM ((64 * 128 + 64 * 130) * 4)

__global__ __launch_bounds__(256, 1)
void k3(const float* __restrict__ ow, const float* __restrict__ ob,
        float* __restrict__ out) {
    extern __shared__ float sm[];
    float* r2s = sm;             // 64 x 128
    float* ws = sm + 64 * 128;   // 64 x 130

    const int tid = threadIdx.x;
    const int v0 = blockIdx.x * 64;

    for (int i = tid; i < 64 * 32; i += 256)
        ((float4*)r2s)[i] = ((const float4*)g_r2)[i];
    for (int i = tid; i < 64 * 64; i += 256) {
        int r = i >> 6, c = i & 63;
        *(float2*)(ws + r * 130 + 2 * c) = *(const float2*)(ow + (size_t)(v0 + r) * 128 + 2 * c);
    }
    __syncthreads();

    const int vl = tid & 63;
    const int bg = tid >> 6;
    const float obv = ob[v0 + vl];

#pragma unroll 4
    for (int bi = 0; bi < 16; ++bi) {
        int bb = bg * 16 + bi;
        u64t acc = 0ull;
#pragma unroll 16
        for (int h2 = 0; h2 < 64; ++h2)
            fma2(acc, *(const u64t*)(r2s + bb * 128 + 2 * h2),
                      *(const u64t*)(ws + vl * 130 + 2 * h2));
        out[(size_t)bb * Vn + v0 + vl] = hsum(acc) + obv;
    }
}

// ------------------------- launch ------------------------------------------
extern "C" void kernel_launch(void* const* d_in, const int* in_sizes, int n_in,
                              void* d_out, int out_size) {
    (void)in_sizes; (void)n_in; (void)out_size;
    const void*  seq = d_in[0];
    const float* ew  = (const float*)d_in[1];
    const float* w1  = (const float*)d_in[2];
    const float* b1  = (const float*)d_in[3];
    const float* w2  = (const float*)d_in[4];
    const float* b2  = (const float*)d_in[5];
    const float* lng = (const float*)d_in[6];
    const float* lnb = (const float*)d_in[7];
    const float* kpw = (const float*)d_in[8];
    const float* rpw = (const float*)d_in[9];
    const float* rpb = (const float*)d_in[10];
    const float* ow  = (const float*)d_in[11];
    const float* ob  = (const float*)d_in[12];
    float* out = (float*)d_out;

    cudaFuncSetAttribute(kv1,  cudaFuncAttributeMaxDynamicSharedMemorySize, KVT_SMEM);
    cudaFuncSetAttribute(kv2a, cudaFuncAttributeMaxDynamicSharedMemorySize, KVT_SMEM);
    cudaFuncSetAttribute(kv2b, cudaFuncAttributeMaxDynamicSharedMemorySize, KVT_SMEM);
    cudaFuncSetAttribute(kv3,  cudaFuncAttributeMaxDynamicSharedMemorySize, KVT_SMEM);
    cudaFuncSetAttribute(k3,   cudaFuncAttributeMaxDynamicSharedMemorySize, K3_SMEM);

    k0_detect<<<1, 256>>>((const unsigned int*)seq);
    kv1 <<<296, 256, KVT_SMEM>>>(ew, w1, b1, 0);
    kv1 <<<296, 256, KVT_SMEM>>>(ew, w1, b1, 128);
    kv2a<<<296, 256, KVT_SMEM>>>(w2);
    kv2b<<<296, 256, KVT_SMEM>>>(ew, w2, b2, lng, lnb);
    kv3 <<<296, 256, KVT_SMEM>>>(kpw);
    k2_scan<<<Bn, 512>>>(seq);
    k2b<<<Bn, 128>>>(rpw, rpb);
    k3<<<Vn / 64, 256, K3_SMEM>>>(ow, ob, out);
}

// round 14
// speedup vs baseline: 1.2976x; 1.2976x over previous
#include <cuda_runtime.h>
#include <cuda_bf16.h>
#include <cstdint>

// ---------------------------------------------------------------------------
// AdaptiveEMAModel. Committed scan (R11/R12: 256-thread, single-bar,
// branchless, vocab-table reads — 4 redesigns all regressed, frozen now).
// R14: preprocess GEMMs use TRANSPOSED W in smem (Wsm[hh][out], pitch 132):
//  - W loads lane-consecutive LDS.128 (was 4-way bank conflict at stride 132)
//  - X loads warp-broadcast LDS.128
//  - accumulators are output-pairs -> no hsum epilogue, float4 stores.
// ---------------------------------------------------------------------------

typedef unsigned long long u64t;

__device__ __forceinline__ u64t pk2(float lo, float hi) {
    u64t r;
    asm("mov.b64 %0, {%1, %2};" : "=l"(r) : "f"(lo), "f"(hi));
    return r;
}
__device__ __forceinline__ void fma2(u64t& d, u64t a, u64t b) {
    asm("fma.rn.f32x2 %0, %1, %2, %0;" : "+l"(d) : "l"(a), "l"(b));
}
__device__ __forceinline__ float2 upk(u64t v) {
    float2 f;
    asm("mov.b64 {%0, %1}, %2;" : "=f"(f.x), "=f"(f.y) : "l"(v));
    return f;
}
__device__ __forceinline__ float hsum(u64t v) {
    float2 f = upk(v);
    return f.x + f.y;
}

#define Bn   64
#define Ln   2048
#define Hn   128
#define H2n  256
#define Vn   32000
#define NTOK (Bn * Ln)

// ------------------------- global scratch ----------------------------------
__device__ __align__(16) float g_y[(size_t)Vn * H2n];      // 32.8 MB
__device__ __align__(16) float g_part[(size_t)Vn * Hn];    // 16.4 MB
__device__ __align__(16) float g_hln[(size_t)Vn * Hn];     // 16.4 MB
__device__ __align__(16) float g_Kv[(size_t)Vn * Hn];      // raw k per vocab
__device__ __align__(16) float g_KNv[(size_t)Vn * Hn];     // normalized k
__device__ __align__(16) float g_THv[Vn];                  // (0.4*||k||)^2
__device__ __align__(16) float g_read[Bn * Hn];
__device__ __align__(16) float g_r2[Bn * Hn];
__device__ int g_is64;

// ------------------------- K0: detect seq dtype ----------------------------
__global__ void k0_detect(const unsigned int* __restrict__ sw) {
    int t = threadIdx.x;
    int nz = (sw[2 * t + 1] != 0u) ? 1 : 0;
    nz = __syncthreads_or(nz);
    if (t == 0) g_is64 = nz ? 0 : 1;
}

// ------------------------- transposed GEMM core ----------------------------
// Wsm[hh][out] pitch 132 (128 reduction rows x 128 outputs).
// Xsm[tok][hh] pitch 132 (32 tokens).
// Warp w owns tokens tg=w*4..+3; lane owns outputs 4*lane..4*lane+3.
// accL[i] = outputs (4l, 4l+1), accH[i] = outputs (4l+2, 4l+3) for token i.
#define KVT_SMEM ((128 * 132 + 32 * 132) * 4)

__device__ __forceinline__ void gemm_core_t(const float* __restrict__ Wsm,
                                            const float* __restrict__ Xsm,
                                            int tg, int lane,
                                            u64t accL[4], u64t accH[4]) {
    const float4* W4 = (const float4*)Wsm;   // row pitch 33 float4
    const float4* X4 = (const float4*)Xsm;
#pragma unroll
    for (int i = 0; i < 4; ++i) { accL[i] = 0ull; accH[i] = 0ull; }
#pragma unroll 2
    for (int hb = 0; hb < 32; ++hb) {
        float4 w0 = W4[(4 * hb + 0) * 33 + lane];
        float4 w1 = W4[(4 * hb + 1) * 33 + lane];
        float4 w2 = W4[(4 * hb + 2) * 33 + lane];
        float4 w3 = W4[(4 * hb + 3) * 33 + lane];
        u64t w0l = pk2(w0.x, w0.y), w0h = pk2(w0.z, w0.w);
        u64t w1l = pk2(w1.x, w1.y), w1h = pk2(w1.z, w1.w);
        u64t w2l = pk2(w2.x, w2.y), w2h = pk2(w2.z, w2.w);
        u64t w3l = pk2(w3.x, w3.y), w3h = pk2(w3.z, w3.w);
#pragma unroll
        for (int i = 0; i < 4; ++i) {
            float4 x = X4[(tg + i) * 33 + hb];   // warp-broadcast
            u64t xx = pk2(x.x, x.x);
            u64t xy = pk2(x.y, x.y);
            u64t xz = pk2(x.z, x.z);
            u64t xw = pk2(x.w, x.w);
            fma2(accL[i], xx, w0l); fma2(accH[i], xx, w0h);
            fma2(accL[i], xy, w1l); fma2(accH[i], xy, w1h);
            fma2(accL[i], xz, w2l); fma2(accH[i], xz, w2h);
            fma2(accL[i], xw, w3l); fma2(accH[i], xw, w3h);
        }
    }
}

// stage a 128x128 weight panel transposed: Wsm[hh*132 + out] = src[out][hh]
__device__ __forceinline__ void stage_wt(float* Wsm, const float* __restrict__ src,
                                         int rstride, int tid) {
    for (int i = tid; i < 128 * 32; i += 256) {
        int out = i >> 5, hb = i & 31;
        float4 v = *(const float4*)(src + (size_t)out * rstride + 4 * hb);
        Wsm[(4 * hb + 0) * 132 + out] = v.x;
        Wsm[(4 * hb + 1) * 132 + out] = v.y;
        Wsm[(4 * hb + 2) * 132 + out] = v.z;
        Wsm[(4 * hb + 3) * 132 + out] = v.w;
    }
}
// stage a 32x128 activation tile (row stride rstride floats) pitch 132
__device__ __forceinline__ void stage_x(float* Xsm, const float* __restrict__ src,
                                        int rstride, int tid) {
    for (int i = tid; i < 32 * 32; i += 256) {
        int tk = i >> 5, q = i & 31;
        *(float4*)(Xsm + tk * 132 + 4 * q) = *(const float4*)(src + (size_t)tk * rstride + 4 * q);
    }
}

// ------------------------- KV1: FFN layer 1 (one output half) --------------
__global__ __launch_bounds__(256, 2)
void kv1(const float* __restrict__ ew, const float* __restrict__ w1,
         const float* __restrict__ b1, int obase) {
    extern __shared__ float sm[];
    float* W = sm;
    float* X = sm + 128 * 132;

    const int tid = threadIdx.x;
    const int lane = tid & 31;
    const int tg = (tid >> 5) * 4;

    stage_wt(W, w1 + (size_t)obase * 128, 128, tid);
    const float4 bb = *(const float4*)(b1 + obase + 4 * lane);
    __syncthreads();

    for (int tile = blockIdx.x; tile < Vn / 32; tile += gridDim.x) {
        const int v0 = tile * 32;
        stage_x(X, ew + (size_t)v0 * 128, 128, tid);
        __syncthreads();

        u64t accL[4], accH[4];
        gemm_core_t(W, X, tg, lane, accL, accH);

#pragma unroll
        for (int i = 0; i < 4; ++i) {
            float2 lo = upk(accL[i]), hi = upk(accH[i]);
            float4 y;
            y.x = fmaxf(lo.x + bb.x, 0.0f);
            y.y = fmaxf(lo.y + bb.y, 0.0f);
            y.z = fmaxf(hi.x + bb.z, 0.0f);
            y.w = fmaxf(hi.y + bb.w, 0.0f);
            *(float4*)(g_y + (size_t)(v0 + tg + i) * H2n + obase + 4 * lane) = y;
        }
        __syncthreads();
    }
}

// ------------------------- KV2a: FFN layer 2, reduction half 0 -> partial --
__global__ __launch_bounds__(256, 2)
void kv2a(const float* __restrict__ w2) {
    extern __shared__ float sm[];
    float* W = sm;
    float* X = sm + 128 * 132;

    const int tid = threadIdx.x;
    const int lane = tid & 31;
    const int tg = (tid >> 5) * 4;

    stage_wt(W, w2, 256, tid);          // w2[o][0..127]
    __syncthreads();

    for (int tile = blockIdx.x; tile < Vn / 32; tile += gridDim.x) {
        const int v0 = tile * 32;
        stage_x(X, g_y + (size_t)v0 * H2n, H2n, tid);   // Y cols 0..127
        __syncthreads();

        u64t accL[4], accH[4];
        gemm_core_t(W, X, tg, lane, accL, accH);

#pragma unroll
        for (int i = 0; i < 4; ++i) {
            float2 lo = upk(accL[i]), hi = upk(accH[i]);
            float4 p = make_float4(lo.x, lo.y, hi.x, hi.y);
            *(float4*)(g_part + (size_t)(v0 + tg + i) * Hn + 4 * lane) = p;
        }
        __syncthreads();
    }
}

// ------------------------- KV2b: reduction half 1 + bias + residual + LN ---
__global__ __launch_bounds__(256, 2)
void kv2b(const float* __restrict__ ew, const float* __restrict__ w2,
          const float* __restrict__ b2,
          const float* __restrict__ lng, const float* __restrict__ lnb) {
    extern __shared__ float sm[];
    float* W = sm;
    float* X = sm + 128 * 132;

    const int tid = threadIdx.x;
    const int lane = tid & 31;
    const int tg = (tid >> 5) * 4;

    stage_wt(W, w2 + 128, 256, tid);    // w2[o][128..255]
    const float4 b2r = *(const float4*)(b2 + 4 * lane);
    const float4 gr  = *(const float4*)(lng + 4 * lane);
    const float4 br  = *(const float4*)(lnb + 4 * lane);
    __syncthreads();

    for (int tile = blockIdx.x; tile < Vn / 32; tile += gridDim.x) {
        const int v0 = tile * 32;
        stage_x(X, g_y + (size_t)v0 * H2n + 128, H2n, tid);   // Y cols 128..255
        __syncthreads();

        u64t accL[4], accH[4];
        gemm_core_t(W, X, tg, lane, accL, accH);

#pragma unroll
        for (int i = 0; i < 4; ++i) {
            const size_t tok = (size_t)(v0 + tg + i);
            float2 lo = upk(accL[i]), hi = upk(accH[i]);
            float4 pp = *(const float4*)(g_part + tok * Hn + 4 * lane);
            float4 rr = *(const float4*)(ew + tok * 128 + 4 * lane);
            float x[4];
            x[0] = lo.x + pp.x + b2r.x + rr.x;
            x[1] = lo.y + pp.y + b2r.y + rr.y;
            x[2] = hi.x + pp.z + b2r.z + rr.z;
            x[3] = hi.y + pp.w + b2r.w + rr.w;
            float s = x[0] + x[1] + x[2] + x[3];
#pragma unroll
            for (int off = 16; off; off >>= 1) s += __shfl_xor_sync(0xffffffffu, s, off);
            float mu = s * (1.0f / 128.0f);
            float vs = 0.0f;
#pragma unroll
            for (int j = 0; j < 4; ++j) { float dv = x[j] - mu; vs += dv * dv; }
#pragma unroll
            for (int off = 16; off; off >>= 1) vs += __shfl_xor_sync(0xffffffffu, vs, off);
            float den = sqrtf(vs * (1.0f / 128.0f) + 1e-5f);
            float4 h;
            h.x = (x[0] - mu) / den * gr.x + br.x;
            h.y = (x[1] - mu) / den * gr.y + br.y;
            h.z = (x[2] - mu) / den * gr.z + br.z;
            h.w = (x[3] - mu) / den * gr.w + br.w;
            *(float4*)(g_hln + tok * Hn + 4 * lane) = h;
        }
        __syncthreads();
    }
}

// ------------------------- KV3: kproj + norm/kn/threshold ------------------
__global__ __launch_bounds__(256, 2)
void kv3(const float* __restrict__ kpw) {
    extern __shared__ float sm[];
    float* W = sm;
    float* X = sm + 128 * 132;

    const int tid = threadIdx.x;
    const int lane = tid & 31;
    const int tg = (tid >> 5) * 4;

    stage_wt(W, kpw, 128, tid);
    __syncthreads();

    for (int tile = blockIdx.x; tile < Vn / 32; tile += gridDim.x) {
        const int v0 = tile * 32;
        stage_x(X, g_hln + (size_t)v0 * Hn, Hn, tid);
        __syncthreads();

        u64t accL[4], accH[4];
        gemm_core_t(W, X, tg, lane, accL, accH);

#pragma unroll
        for (int i = 0; i < 4; ++i) {
            const size_t tok = (size_t)(v0 + tg + i);
            float2 lo = upk(accL[i]), hi = upk(accH[i]);
            float kvv[4] = {lo.x, lo.y, hi.x, hi.y};
            *(float4*)(g_Kv + tok * Hn + 4 * lane) = make_float4(kvv[0], kvv[1], kvv[2], kvv[3]);
            float s = kvv[0] * kvv[0] + kvv[1] * kvv[1] + kvv[2] * kvv[2] + kvv[3] * kvv[3];
#pragma unroll
            for (int off = 16; off; off >>= 1) s += __shfl_xor_sync(0xffffffffu, s, off);
            float nm = fmaxf(sqrtf(s), 1e-12f);
            float inv = 1.0f / nm;
            *(float4*)(g_KNv + tok * Hn + 4 * lane) =
                make_float4(kvv[0] * inv, kvv[1] * inv, kvv[2] * inv, kvv[3] * inv);
            if (lane == 0) {
                float t1 = 0.4f * nm;
                g_THv[tok] = t1 * t1;
            }
        }
        __syncthreads();
    }
}

// ------------------------- K2: delta-rule scan (R11/R12 committed) ---------
__global__ __launch_bounds__(256, 1)
void k2_scan(const void* __restrict__ seq) {
    const int b = blockIdx.x;
    const int tid = threadIdx.x;
    const int lane = tid & 31;
    const int w = tid >> 5;
    const int row = tid >> 1;
    const int half = tid & 1;

    __shared__ int   idxs[Ln];
    __shared__ float ths[Ln];
    __shared__ __align__(16) float kns[8][136];   // kn ring, slot = t & 7
    __shared__ __align__(16) float red[2][8];

    const int is64 = g_is64;
    for (int i = tid; i < Ln; i += 256) {
        long long idx = is64 ? ((const long long*)seq)[(size_t)b * Ln + i]
                             : (long long)((const int*)seq)[(size_t)b * Ln + i];
        idxs[i] = (int)idx;
        ths[i] = g_THv[idx];
    }
    __syncthreads();

    const int pos = 68 * (row >> 6) + (row & 63);
    if (half == 0) {
        kns[0][pos] = g_KNv[(size_t)idxs[0] * Hn + row];
        kns[1][pos] = g_KNv[(size_t)idxs[1] * Hn + row];
    }
    float Lprev = g_KNv[(size_t)idxs[2] * Hn + row];
    float kcur = g_Kv[(size_t)idxs[0] * Hn + row];
    float knx1 = g_Kv[(size_t)idxs[1] * Hn + row];
    float knx2 = g_Kv[(size_t)idxs[2] * Hn + row];
    float thc  = ths[0];

    u64t M[32];
#pragma unroll
    for (int c = 0; c < 32; ++c) M[c] = 0ull;
    __syncthreads();

#pragma unroll 2
    for (int t = 0; t < Ln - 1; ++t) {
        const int tp = t + 3;
        float Lnew = 0.0f;
        if (tp < Ln - 1)       Lnew = g_KNv[(size_t)idxs[tp] * Hn + row];
        else if (tp == Ln - 1) Lnew = g_Kv[(size_t)idxs[Ln - 1] * Hn + row];
        const int tk = (tp < Ln) ? tp : Ln - 1;
        float knew = g_Kv[(size_t)idxs[tk] * Hn + row];
        float thn = ths[(t + 1 < Ln) ? t + 1 : t];

        if (half == 0) kns[(t + 2) & 7][pos] = Lprev;

        const float4* knT4 = (const float4*)(kns[t & 7] + 68 * half);
        u64t kr[32];
        u64t a0 = 0ull, a1 = 0ull, a2 = 0ull, a3 = 0ull;
#pragma unroll
        for (int cc = 0; cc < 8; ++cc) {
            float4 v0 = knT4[2 * cc];
            float4 v1 = knT4[2 * cc + 1];
            kr[4 * cc]     = pk2(v0.x, v0.y);
            kr[4 * cc + 1] = pk2(v0.z, v0.w);
            kr[4 * cc + 2] = pk2(v1.x, v1.y);
            kr[4 * cc + 3] = pk2(v1.z, v1.w);
            fma2(a0, M[4 * cc],     kr[4 * cc]);
            fma2(a1, M[4 * cc + 1], kr[4 * cc + 1]);
            fma2(a2, M[4 * cc + 2], kr[4 * cc + 2]);
            fma2(a3, M[4 * cc + 3], kr[4 * cc + 3]);
        }
        float vph = (hsum(a0) + hsum(a1)) + (hsum(a2) + hsum(a3));
        float vp = vph + __shfl_xor_sync(0xffffffffu, vph, 1);
        float d = kcur - vp;

        float dsq = d * d;
        dsq += __shfl_xor_sync(0xffffffffu, dsq, 2);
        dsq += __shfl_xor_sync(0xffffffffu, dsq, 4);
        dsq += __shfl_xor_sync(0xffffffffu, dsq, 8);
        dsq += __shfl_xor_sync(0xffffffffu, dsq, 16);
        if (lane == 0) red[t & 1][w] = dsq;
        __syncthreads();

        float4 r0 = *(const float4*)&red[t & 1][0];
        float4 r1 = *(const float4*)&red[t & 1][4];
        float dd = ((r0.x + r0.y) + (r0.z + r0.w)) + ((r1.x + r1.y) + (r1.z + r1.w));

        float s = (dd >= thc) ? d * (1.0f / 2048.0f) : 0.0f;
        u64t s2 = pk2(s, s);
#pragma unroll
        for (int c = 0; c < 32; ++c) fma2(M[c], s2, kr[c]);

        kcur = knx1; knx1 = knx2; knx2 = knew;
        thc = thn;
        Lprev = Lnew;
    }

    __syncthreads();
    {
        const float4* q4 = (const float4*)(kns[(Ln - 1) & 7] + 68 * half);
        u64t a0 = 0ull, a1 = 0ull;
#pragma unroll
        for (int cc = 0; cc < 16; ++cc) {
            float4 v = q4[cc];
            fma2(a0, M[2 * cc], pk2(v.x, v.y));
            fma2(a1, M[2 * cc + 1], pk2(v.z, v.w));
        }
        float vph = hsum(a0) + hsum(a1);
        float rd = vph + __shfl_xor_sync(0xffffffffu, vph, 1);
        if (half == 0) g_read[b * Hn + row] = rd;
    }
}

// ------------------------- K2b: r2 = read @ rp_w^T + rp_b ------------------
__global__ void k2b(const float* __restrict__ rpw, const float* __restrict__ rpb) {
    __shared__ __align__(16) float rs[128];
    const int b = blockIdx.x, tid = threadIdx.x;
    rs[tid] = g_read[b * Hn + tid];
    __syncthreads();
    const u64t* rp = (const u64t*)rs;
    u64t acc = 0ull;
#pragma unroll 8
    for (int j2 = 0; j2 < 64; ++j2) {
        u64t wv = *(const u64t*)(rpw + tid * 128 + 2 * j2);
        fma2(acc, rp[j2], wv);
    }
    g_r2[b * Hn + tid] = hsum(acc) + rpb[tid];
}

// ------------------------- K3: out = r2 @ out_w^T + out_b ------------------
#define K3_SMEM ((64 * 128 + 64 * 130) * 4)

__global__ __launch_bounds__(256, 1)
void k3(const float* __restrict__ ow, const float* __restrict__ ob,
        float* __restrict__ out) {
    extern __shared__ float sm[];
    float* r2s = sm;             // 64 x 128
    float* ws = sm + 64 * 128;   // 64 x 130

    const int tid = threadIdx.x;
    const int v0 = blockIdx.x * 64;

    for (int i = tid; i < 64 * 32; i += 256)
        ((float4*)r2s)[i] = ((const float4*)g_r2)[i];
    for (int i = tid; i < 64 * 64; i += 256) {
        int r = i >> 6, c = i & 63;
        *(float2*)(ws + r * 130 + 2 * c) = *(const float2*)(ow + (size_t)(v0 + r) * 128 + 2 * c);
    }
    __syncthreads();

    const int vl = tid & 63;
    const int bg = tid >> 6;
    const float obv = ob[v0 + vl];

#pragma unroll 4
    for (int bi = 0; bi < 16; ++bi) {
        int bb = bg * 16 + bi;
        u64t acc = 0ull;
#pragma unroll 16
        for (int h2 = 0; h2 < 64; ++h2)
            fma2(acc, *(const u64t*)(r2s + bb * 128 + 2 * h2),
                      *(const u64t*)(ws + vl * 130 + 2 * h2));
        out[(size_t)bb * Vn + v0 + vl] = hsum(acc) + obv;
    }
}

// ------------------------- launch ------------------------------------------
extern "C" void kernel_launch(void* const* d_in, const int* in_sizes, int n_in,
                              void* d_out, int out_size) {
    (void)in_sizes; (void)n_in; (void)out_size;
    const void*  seq = d_in[0];
    const float* ew  = (const float*)d_in[1];
    const float* w1  = (const float*)d_in[2];
    const float* b1  = (const float*)d_in[3];
    const float* w2  = (const float*)d_in[4];
    const float* b2  = (const float*)d_in[5];
    const float* lng = (const float*)d_in[6];
    const float* lnb = (const float*)d_in[7];
    const float* kpw = (const float*)d_in[8];
    const float* rpw = (const float*)d_in[9];
    const float* rpb = (const float*)d_in[10];
    const float* ow  = (const float*)d_in[11];
    const float* ob  = (const float*)d_in[12];
    float* out = (float*)d_out;

    cudaFuncSetAttribute(kv1,  cudaFuncAttributeMaxDynamicSharedMemorySize, KVT_SMEM);
    cudaFuncSetAttribute(kv2a, cudaFuncAttributeMaxDynamicSharedMemorySize, KVT_SMEM);
    cudaFuncSetAttribute(kv2b, cudaFuncAttributeMaxDynamicSharedMemorySize, KVT_SMEM);
    cudaFuncSetAttribute(kv3,  cudaFuncAttributeMaxDynamicSharedMemorySize, KVT_SMEM);
    cudaFuncSetAttribute(k3,   cudaFuncAttributeMaxDynamicSharedMemorySize, K3_SMEM);

    k0_detect<<<1, 256>>>((const unsigned int*)seq);
    kv1 <<<296, 256, KVT_SMEM>>>(ew, w1, b1, 0);
    kv1 <<<296, 256, KVT_SMEM>>>(ew, w1, b1, 128);
    kv2a<<<296, 256, KVT_SMEM>>>(w2);
    kv2b<<<296, 256, KVT_SMEM>>>(ew, w2, b2, lng, lnb);
    kv3 <<<296, 256, KVT_SMEM>>>(kpw);
    k2_scan<<<Bn, 256>>>(seq);
    k2b<<<Bn, 128>>>(rpw, rpb);
    k3<<<Vn / 64, 256, K3_SMEM>>>(ow, ob, out);
}